// round 13
// baseline (speedup 1.0000x reference)
#include <cuda_runtime.h>
#include <math.h>

// Problem constants
#define N1 200000
#define NB 8
#define NPG 25000
#define NN2 199
#define KSEL 50
#define FDIM 128

// packed fp32 ops (sm_103a FFMA2 path — only reachable via PTX f32x2)
#define PACK_F32X2(out, lo, hi) \
    asm("mov.b64 %0, {%1, %2};" : "=l"(out) : "f"(lo), "f"(hi))
#define UNPACK_F32X2(lo, hi, in) \
    asm("mov.b64 {%0, %1}, %2;" : "=f"(lo), "=f"(hi) : "l"(in))
#define FMA_F32X2(d, a, b, c) \
    asm("fma.rn.f32x2 %0, %1, %2, %3;" : "=l"(d) : "l"(a), "l"(b), "l"(c))

// -------- scratch (device globals; no allocation allowed) --------
__device__ float g_agg[200000 * 128];
__device__ float g_h[200000 * 128];
__device__ float g_out1[200000 * 64];
__device__ float g_agg2[199 * 128];
__device__ float g_h2[199 * 128];
__device__ float g_out2[199 * 64];
__device__ float g_key[200000];
__device__ int   g_top[8 * 50];
__device__ float g_pooled[8 * 50 * 199];
__device__ float g_fc1[8 * 128];
__device__ int   g_ei1[2 * 2000000];   // canonical int32 edge index, graph 1
__device__ int   g_ei2[2 * 4000];      // canonical int32 edge index, graph 2
__device__ unsigned int g_flag[2];     // dtype-detect flags (per edge list)

static inline int imin(int a, int b) { return a < b ? a : b; }

// -------- zero kernel (avoid memset nodes; pure kernel work) --------
__global__ void zero_kernel(float4* p, int n4) {
    int i = blockIdx.x * blockDim.x + threadIdx.x;
    int stride = gridDim.x * blockDim.x;
    float4 z = make_float4(0.f, 0.f, 0.f, 0.f);
    for (; i < n4; i += stride) p[i] = z;
}

__global__ void zero_flags_kernel(unsigned int* f) {
    f[0] = 0; f[1] = 0;
}

// -------- edge dtype detect: OR all odd 32-bit words ---------------------
// if the buffer holds int64 values < 2^31, every odd word is 0 -> flag==0.
// if it holds int32 edge data, flag ~surely becomes nonzero.
__global__ void detect_kernel(const unsigned int* __restrict__ buf, int nvals,
                              unsigned int* flag) {
    unsigned int acc = 0;
    int i = blockIdx.x * blockDim.x + threadIdx.x;
    int stride = gridDim.x * blockDim.x;
    for (; i < nvals; i += stride) acc |= buf[2 * i + 1];
#pragma unroll
    for (int o = 16; o; o >>= 1) acc |= __shfl_xor_sync(0xffffffffu, acc, o);
    if ((threadIdx.x & 31) == 0 && acc) atomicOr(flag, acc);
}

// -------- convert edge index to canonical int32 --------------------------
__global__ void convert_idx_kernel(const void* __restrict__ buf, int nvals,
                                   const unsigned int* __restrict__ flag,
                                   int* __restrict__ out) {
    bool is32 = (*flag != 0u);
    int i = blockIdx.x * blockDim.x + threadIdx.x;
    int stride = gridDim.x * blockDim.x;
    if (is32) {
        const int* b = (const int*)buf;
        for (; i < nvals; i += stride) out[i] = b[i];
    } else {
        const long long* b = (const long long*)buf;
        for (; i < nvals; i += stride) out[i] = (int)b[i];
    }
}

// -------- scatter-add aggregation: agg[dst] += x[src], D=128 --------
// one warp per edge; vector reduction (16B RED messages)
// unsigned bounds guard: out-of-range edges are skipped (never taken for
// valid data; turns a would-be crash into an observable rel_err signal)
__global__ void agg_kernel(const float* __restrict__ x,
                           const int* __restrict__ src,
                           const int* __restrict__ dst,
                           int E, int Nmax, float* __restrict__ agg) {
    int gw = (blockIdx.x * blockDim.x + threadIdx.x) >> 5;
    int lane = threadIdx.x & 31;
    int nw = (gridDim.x * blockDim.x) >> 5;
    for (int e = gw; e < E; e += nw) {
        int s = __ldg(src + e);
        int d = __ldg(dst + e);
        if ((unsigned)s >= (unsigned)Nmax || (unsigned)d >= (unsigned)Nmax) continue;
        float4 v = __ldg((const float4*)(x + (size_t)s * 128) + lane);
        float* p = agg + (size_t)d * 128 + lane * 4;
        asm volatile("red.global.add.v4.f32 [%0], {%1,%2,%3,%4};"
                     :: "l"(p), "f"(v.x), "f"(v.y), "f"(v.z), "f"(v.w)
                     : "memory");
    }
}

// -------- fused GIN MLP: out = relu(W2^T relu(W1^T (x+agg) + b1) + b2) ----
// input dim is always 128; C1 = hidden dim, C2 = out dim
// inner products use packed fma.rn.f32x2 (FFMA2): halves FMA-pipe pressure
template <int C1, int C2>
__global__ void __launch_bounds__(256)
gin_mlp_kernel(const float* __restrict__ x, const float* __restrict__ agg, int M,
               const float* __restrict__ W1, const float* __restrict__ b1,
               const float* __restrict__ W2, const float* __restrict__ b2,
               float* __restrict__ out) {
    const int TM = 64;
    extern __shared__ float sm[];
    float* sW1 = sm;                    // 128*C1
    float* sW2 = sW1 + 128 * C1;        // C1*C2
    float* sb1 = sW2 + C1 * C2;         // C1
    float* sb2 = sb1 + C1;              // C2
    float* sIn = sb2 + C2;              // TM * 132
    float* sT  = sIn + TM * 132;        // TM * (C1+4)
    int tid = threadIdx.x;

    for (int i = tid; i < 128 * C1 / 4; i += 256)
        ((float4*)sW1)[i] = __ldg((const float4*)W1 + i);
    for (int i = tid; i < C1 * C2 / 4; i += 256)
        ((float4*)sW2)[i] = __ldg((const float4*)W2 + i);
    if (tid < C1) sb1[tid] = b1[tid];
    if (tid < C2) sb2[tid] = b2[tid];

    int numTiles = (M + TM - 1) / TM;
    for (int tile = blockIdx.x; tile < numTiles; tile += gridDim.x) {
        int row0 = tile * TM;
        __syncthreads();
        // load (x + agg) tile into smem
        for (int i = tid; i < TM * 32; i += 256) {
            int r = i >> 5, c = i & 31;
            int row = row0 + r;
            float4 v = make_float4(0.f, 0.f, 0.f, 0.f);
            if (row < M) {
                float4 a = __ldg((const float4*)(x + (size_t)row * 128) + c);
                float4 b = __ldg((const float4*)(agg + (size_t)row * 128) + c);
                v.x = a.x + b.x; v.y = a.y + b.y; v.z = a.z + b.z; v.w = a.w + b.w;
            }
            *((float4*)(sIn + r * 132) + c) = v;
        }
        __syncthreads();
        // phase 1: T = relu(In @ W1 + b1)   [TM x C1]
        {
            const int CT = C1 / 4, RT = 256 / CT, RPT = TM / RT;
            int tx = tid % CT, ty = tid / CT;
            unsigned long long acc2[RPT][2];
            {
                unsigned long long b01, b23;
                PACK_F32X2(b01, sb1[4 * tx + 0], sb1[4 * tx + 1]);
                PACK_F32X2(b23, sb1[4 * tx + 2], sb1[4 * tx + 3]);
#pragma unroll
                for (int i = 0; i < RPT; i++) { acc2[i][0] = b01; acc2[i][1] = b23; }
            }
#pragma unroll 4
            for (int k = 0; k < 128; k++) {
                float4 w = *((float4*)(sW1 + k * C1) + tx);
                unsigned long long w01, w23;
                PACK_F32X2(w01, w.x, w.y);
                PACK_F32X2(w23, w.z, w.w);
#pragma unroll
                for (int i = 0; i < RPT; i++) {
                    float a = sIn[(ty * RPT + i) * 132 + k];
                    unsigned long long aa;
                    PACK_F32X2(aa, a, a);
                    FMA_F32X2(acc2[i][0], aa, w01, acc2[i][0]);
                    FMA_F32X2(acc2[i][1], aa, w23, acc2[i][1]);
                }
            }
#pragma unroll
            for (int i = 0; i < RPT; i++) {
                float4 v;
                UNPACK_F32X2(v.x, v.y, acc2[i][0]);
                UNPACK_F32X2(v.z, v.w, acc2[i][1]);
                v.x = fmaxf(v.x, 0.f); v.y = fmaxf(v.y, 0.f);
                v.z = fmaxf(v.z, 0.f); v.w = fmaxf(v.w, 0.f);
                *((float4*)(sT + (ty * RPT + i) * (C1 + 4)) + tx) = v;
            }
        }
        __syncthreads();
        // phase 2: Out = relu(T @ W2 + b2)   [TM x C2]
        {
            const int CT = C2 / 4, RT = 256 / CT, RPT = TM / RT;
            int tx = tid % CT, ty = tid / CT;
            unsigned long long acc2[RPT][2];
            {
                unsigned long long b01, b23;
                PACK_F32X2(b01, sb2[4 * tx + 0], sb2[4 * tx + 1]);
                PACK_F32X2(b23, sb2[4 * tx + 2], sb2[4 * tx + 3]);
#pragma unroll
                for (int i = 0; i < RPT; i++) { acc2[i][0] = b01; acc2[i][1] = b23; }
            }
#pragma unroll 4
            for (int k = 0; k < C1; k++) {
                float4 w = *((float4*)(sW2 + k * C2) + tx);
                unsigned long long w01, w23;
                PACK_F32X2(w01, w.x, w.y);
                PACK_F32X2(w23, w.z, w.w);
#pragma unroll
                for (int i = 0; i < RPT; i++) {
                    float a = sT[(ty * RPT + i) * (C1 + 4) + k];
                    unsigned long long aa;
                    PACK_F32X2(aa, a, a);
                    FMA_F32X2(acc2[i][0], aa, w01, acc2[i][0]);
                    FMA_F32X2(acc2[i][1], aa, w23, acc2[i][1]);
                }
            }
#pragma unroll
            for (int i = 0; i < RPT; i++) {
                int row = row0 + ty * RPT + i;
                if (row < M) {
                    float4 v;
                    UNPACK_F32X2(v.x, v.y, acc2[i][0]);
                    UNPACK_F32X2(v.z, v.w, acc2[i][1]);
                    v.x = fmaxf(v.x, 0.f); v.y = fmaxf(v.y, 0.f);
                    v.z = fmaxf(v.z, 0.f); v.w = fmaxf(v.w, 0.f);
                    *((float4*)(out + (size_t)row * C2) + tx) = v;
                }
            }
        }
    }
}

// -------- key[i] = dist(out1[i], out2[198])  (reference cdist formula) ----
__global__ void key_kernel(const float* __restrict__ out1,
                           const float* __restrict__ out2last,
                           float* __restrict__ key, int M) {
    int gw = (blockIdx.x * blockDim.x + threadIdx.x) >> 5;
    int lane = threadIdx.x & 31;
    int nw = (gridDim.x * blockDim.x) >> 5;
    float2 b = ((const float2*)out2last)[lane];
    float n2 = b.x * b.x + b.y * b.y;
#pragma unroll
    for (int o = 16; o; o >>= 1) n2 += __shfl_xor_sync(0xffffffffu, n2, o);
    for (int i = gw; i < M; i += nw) {
        float2 a = __ldg((const float2*)(out1 + (size_t)i * 64) + lane);
        float dot = a.x * b.x + a.y * b.y;
        float n1 = a.x * a.x + a.y * a.y;
#pragma unroll
        for (int o = 16; o; o >>= 1) {
            dot += __shfl_xor_sync(0xffffffffu, dot, o);
            n1 += __shfl_xor_sync(0xffffffffu, n1, o);
        }
        if (lane == 0) key[i] = sqrtf(fmaxf(n1 + n2 - 2.f * dot, 0.f));
    }
}

// -------- exact top-50 per graph (desc by value, ties -> lower index) -----
__global__ void topk_kernel(const float* __restrict__ key, int* __restrict__ top) {
    extern __shared__ float sk[];          // NPG floats
    __shared__ float sval[32];
    __shared__ int sidx[32];
    int g = blockIdx.x, tid = threadIdx.x;
    const float* kg = key + g * NPG;
    for (int i = tid; i < NPG; i += blockDim.x) sk[i] = kg[i];
    __syncthreads();
    for (int r = 0; r < KSEL; r++) {
        float bv = -3.0e38f; int bi = 0x7fffffff;
        for (int i = tid; i < NPG; i += blockDim.x) {
            float v = sk[i];
            if (v > bv || (v == bv && i < bi)) { bv = v; bi = i; }
        }
#pragma unroll
        for (int o = 16; o; o >>= 1) {
            float ov = __shfl_xor_sync(0xffffffffu, bv, o);
            int oi = __shfl_xor_sync(0xffffffffu, bi, o);
            if (ov > bv || (ov == bv && oi < bi)) { bv = ov; bi = oi; }
        }
        int w = tid >> 5;
        if ((tid & 31) == 0) { sval[w] = bv; sidx[w] = bi; }
        __syncthreads();
        if (w == 0) {
            int nwarp = blockDim.x >> 5;
            bv = (tid < nwarp) ? sval[tid] : -3.0e38f;
            bi = (tid < nwarp) ? sidx[tid] : 0x7fffffff;
#pragma unroll
            for (int o = 16; o; o >>= 1) {
                float ov = __shfl_xor_sync(0xffffffffu, bv, o);
                int oi = __shfl_xor_sync(0xffffffffu, bi, o);
                if (ov > bv || (ov == bv && oi < bi)) { bv = ov; bi = oi; }
            }
            if (tid == 0) {
                top[g * KSEL + r] = g * NPG + bi;
                sk[bi] = -3.0e38f;
            }
        }
        __syncthreads();
    }
}

// -------- full distance rows for the 400 selected nodes ------------------
__global__ void pooled_kernel(const float* __restrict__ out1,
                              const float* __restrict__ out2,
                              const int* __restrict__ top,
                              float* __restrict__ pooled) {
    __shared__ float a[64];
    __shared__ float n1s;
    int slot = blockIdx.x;   // g*50 + rank
    int node = top[slot];
    int tid = threadIdx.x;
    if (tid < 64) a[tid] = out1[(size_t)node * 64 + tid];
    __syncthreads();
    if (tid == 0) {
        float s = 0.f;
        for (int d = 0; d < 64; d++) s += a[d] * a[d];
        n1s = s;
    }
    __syncthreads();
    for (int j = tid; j < NN2; j += blockDim.x) {
        const float* b = out2 + j * 64;
        float dot = 0.f, n2 = 0.f;
#pragma unroll 8
        for (int d = 0; d < 64; d++) {
            float bv = __ldg(b + d);
            dot += a[d] * bv;
            n2 += bv * bv;
        }
        pooled[slot * NN2 + j] = sqrtf(fmaxf(n1s + n2 - 2.f * dot, 0.f));
    }
}

// -------- fc1 partial sums (split K across blocks, atomic combine) -------
__global__ void fc1_kernel(const float* __restrict__ pooled,
                           const float* __restrict__ W,
                           float* __restrict__ out) {
    int g = blockIdx.x, kc = blockIdx.y, c = threadIdx.x;
    int k0 = kc * 1244;
    int k1 = k0 + 1244; if (k1 > 9950) k1 = 9950;
    const float* p = pooled + g * 9950;
    float acc = 0.f;
    for (int k = k0; k < k1; k++) acc += __ldg(p + k) * __ldg(W + (size_t)k * 128 + c);
    atomicAdd(&out[g * 128 + c], acc);
}

// -------- head: +b, LN, relu, fc2, LN, relu, fc3, sigmoid ----------------
__device__ __forceinline__ float block_sum(float v, volatile float* red) {
#pragma unroll
    for (int o = 16; o; o >>= 1) v += __shfl_xor_sync(0xffffffffu, v, o);
    int w = threadIdx.x >> 5;
    if ((threadIdx.x & 31) == 0) red[w] = v;
    __syncthreads();
    float s = red[0] + red[1] + red[2] + red[3];
    __syncthreads();
    return s;
}

__global__ void head_kernel(const float* __restrict__ fc1acc, const float* __restrict__ fc1b,
                            const float* __restrict__ g1, const float* __restrict__ be1,
                            const float* __restrict__ fc2W, const float* __restrict__ fc2b,
                            const float* __restrict__ g2, const float* __restrict__ be2,
                            const float* __restrict__ fc3W, const float* __restrict__ fc3b,
                            float* __restrict__ outp) {
    __shared__ float sh[128];
    __shared__ float red[4];
    int g = blockIdx.x, tid = threadIdx.x;
    float v = fc1acc[g * 128 + tid] + fc1b[tid];
    float mean = block_sum(v, red) * (1.f / 128.f);
    float d = v - mean;
    float var = block_sum(d * d, red) * (1.f / 128.f);
    float h = fmaxf(d * rsqrtf(var + 1e-5f) * g1[tid] + be1[tid], 0.f);
    sh[tid] = h;
    __syncthreads();
    float v2 = 0.f;
    if (tid < 64) {
        v2 = fc2b[tid];
        for (int k = 0; k < 128; k++) v2 += sh[k] * fc2W[k * 64 + tid];
    }
    float s2 = block_sum(tid < 64 ? v2 : 0.f, red);
    float mean2 = s2 * (1.f / 64.f);
    float d2 = v2 - mean2;
    float var2 = block_sum(tid < 64 ? d2 * d2 : 0.f, red) * (1.f / 64.f);
    float t = 0.f;
    if (tid < 64) {
        float h2 = fmaxf(d2 * rsqrtf(var2 + 1e-5f) * g2[tid] + be2[tid], 0.f);
        t = h2 * fc3W[tid];
    }
    float z = block_sum(t, red);
    if (tid == 0) outp[g] = 1.f / (1.f + expf(-(z + fc3b[0])));
}

// ========================= launch ========================================
extern "C" void kernel_launch(void* const* d_in, const int* in_sizes, int n_in,
                              void* d_out, int out_size) {
    const float* x1 = (const float*)d_in[0];
    const void* ei1raw = d_in[1];
    // d_in[2] = batch1 (unused; graphs equal-sized)
    const float* x2 = (const float*)d_in[3];
    const void* ei2raw = d_in[4];
    const float* W1a = (const float*)d_in[5];
    const float* b1a = (const float*)d_in[6];
    const float* W1b = (const float*)d_in[7];
    const float* b1b = (const float*)d_in[8];
    const float* W2a = (const float*)d_in[9];
    const float* b2a = (const float*)d_in[10];
    const float* W2b = (const float*)d_in[11];
    const float* b2b = (const float*)d_in[12];
    const float* fc1W = (const float*)d_in[13];
    const float* fc1b = (const float*)d_in[14];
    const float* g1v = (const float*)d_in[15];
    const float* be1 = (const float*)d_in[16];
    const float* fc2W = (const float*)d_in[17];
    const float* fc2b = (const float*)d_in[18];
    const float* g2v = (const float*)d_in[19];
    const float* be2 = (const float*)d_in[20];
    const float* fc3W = (const float*)d_in[21];
    const float* fc3b = (const float*)d_in[22];
    float* outp = (float*)d_out;

    int n1v = in_sizes[1];          // total elements in edge_index1 (2*E1)
    int n2v = in_sizes[4];          // total elements in edge_index2 (2*E2)
    int E1v = n1v / 2;
    int E2v = n2v / 2;

    float *agg, *h, *out1, *agg2, *h2, *out2, *keyp, *pooled, *fc1acc;
    int *top, *ei1c, *ei2c;
    unsigned int* flags;
    cudaGetSymbolAddress((void**)&agg, g_agg);
    cudaGetSymbolAddress((void**)&h, g_h);
    cudaGetSymbolAddress((void**)&out1, g_out1);
    cudaGetSymbolAddress((void**)&agg2, g_agg2);
    cudaGetSymbolAddress((void**)&h2, g_h2);
    cudaGetSymbolAddress((void**)&out2, g_out2);
    cudaGetSymbolAddress((void**)&keyp, g_key);
    cudaGetSymbolAddress((void**)&top, g_top);
    cudaGetSymbolAddress((void**)&pooled, g_pooled);
    cudaGetSymbolAddress((void**)&fc1acc, g_fc1);
    cudaGetSymbolAddress((void**)&ei1c, g_ei1);
    cudaGetSymbolAddress((void**)&ei2c, g_ei2);
    cudaGetSymbolAddress((void**)&flags, g_flag);

    const int nsm = 152;  // GB300 sm_103a

    size_t smem1 = (size_t)(128 * 128 + 128 * 128 + 128 + 128 + 64 * 132 + 64 * 132) * sizeof(float);
    size_t smem2 = (size_t)(128 * 64 + 64 * 64 + 64 + 64 + 64 * 132 + 64 * 68) * sizeof(float);
    cudaFuncSetAttribute(gin_mlp_kernel<128, 128>,
                         cudaFuncAttributeMaxDynamicSharedMemorySize, (int)smem1);
    cudaFuncSetAttribute(gin_mlp_kernel<64, 64>,
                         cudaFuncAttributeMaxDynamicSharedMemorySize, (int)smem2);
    cudaFuncSetAttribute(topk_kernel,
                         cudaFuncAttributeMaxDynamicSharedMemorySize, NPG * 4);

    // ---- edge-index dtype detection + canonicalization to int32 ----
    // NOTE: detection treats the raw buffer as if it were int64; odd 32-bit
    // words are all-zero iff the data really is int64 (values < 2^31).
    zero_flags_kernel<<<1, 1>>>(flags);
    detect_kernel<<<256, 256>>>((const unsigned int*)ei1raw, n1v / 2, flags + 0);
    detect_kernel<<<16, 256>>>((const unsigned int*)ei2raw, n2v / 2, flags + 1);
    convert_idx_kernel<<<1024, 256>>>(ei1raw, n1v, flags + 0, ei1c);
    convert_idx_kernel<<<16, 256>>>(ei2raw, n2v, flags + 1, ei2c);

    // ---- graph 1 GIN ----
    zero_kernel<<<2048, 256>>>((float4*)agg, N1 * 32);
    agg_kernel<<<2048, 256>>>(x1, ei1c, ei1c + E1v, E1v, N1, agg);
    gin_mlp_kernel<128, 128><<<imin(3125, nsm), 256, smem1>>>(x1, agg, N1, W1a, b1a, W1b, b1b, h);
    zero_kernel<<<2048, 256>>>((float4*)agg, N1 * 32);
    agg_kernel<<<2048, 256>>>(h, ei1c, ei1c + E1v, E1v, N1, agg);
    gin_mlp_kernel<64, 64><<<imin(3125, 2 * nsm), 256, smem2>>>(h, agg, N1, W2a, b2a, W2b, b2b, out1);

    // ---- graph 2 GIN (tiny) ----
    zero_kernel<<<32, 256>>>((float4*)agg2, NN2 * 32);
    agg_kernel<<<16, 256>>>(x2, ei2c, ei2c + E2v, E2v, NN2, agg2);
    gin_mlp_kernel<128, 128><<<4, 256, smem1>>>(x2, agg2, NN2, W1a, b1a, W1b, b1b, h2);
    zero_kernel<<<32, 256>>>((float4*)agg2, NN2 * 32);
    agg_kernel<<<16, 256>>>(h2, ei2c, ei2c + E2v, E2v, NN2, agg2);
    gin_mlp_kernel<64, 64><<<4, 256, smem2>>>(h2, agg2, NN2, W2a, b2a, W2b, b2b, out2);

    // ---- sort-pool shortcut: key = last cdist column, top-50 per graph ----
    key_kernel<<<1024, 256>>>(out1, out2 + 198 * 64, keyp, N1);
    topk_kernel<<<8, 1024, NPG * 4>>>(keyp, top);
    pooled_kernel<<<400, 256>>>(out1, out2, top, pooled);

    // ---- head ----
    zero_kernel<<<1, 256>>>((float4*)fc1acc, 8 * 32);
    fc1_kernel<<<dim3(8, 8), 128>>>(pooled, fc1W, fc1acc);
    head_kernel<<<8, 128>>>(fc1acc, fc1b, g1v, be1, fc2W, fc2b, g2v, be2, fc3W, fc3b, outp);
}

// round 16
// speedup vs baseline: 1.1375x; 1.1375x over previous
#include <cuda_runtime.h>
#include <math.h>

// Problem constants
#define N1 200000
#define NB 8
#define NPG 25000
#define NN2 199
#define KSEL 50
#define FDIM 128

// packed fp32 ops (sm_103a FFMA2 path — only reachable via PTX f32x2)
#define PACK_F32X2(out, lo, hi) \
    asm("mov.b64 %0, {%1, %2};" : "=l"(out) : "f"(lo), "f"(hi))
#define UNPACK_F32X2(lo, hi, in) \
    asm("mov.b64 {%0, %1}, %2;" : "=f"(lo), "=f"(hi) : "l"(in))
#define FMA_F32X2(d, a, b, c) \
    asm("fma.rn.f32x2 %0, %1, %2, %3;" : "=l"(d) : "l"(a), "l"(b), "l"(c))

// -------- scratch (device globals; no allocation allowed) --------
__device__ float g_agg[200000 * 128];   // layer1 agg; layer2: [y | aggy]
__device__ float g_h[200000 * 128];
__device__ float g_out1[200000 * 64];
__device__ float g_agg2[199 * 128];     // graph2: layer1 agg; layer2 [y|aggy]
__device__ float g_h2[199 * 128];
__device__ float g_out2[199 * 64];
__device__ float g_key[200000];
__device__ int   g_top[8 * 50];
__device__ float g_pooled[8 * 50 * 199];
__device__ float g_fc1[8 * 128];
__device__ int   g_ei1[2 * 2000000];
__device__ int   g_ei2[2 * 4000];
__device__ unsigned int g_flag[2];

static inline int imin(int a, int b) { return a < b ? a : b; }

// -------- zero kernel --------
__global__ void zero_kernel(float4* p, int n4) {
    int i = blockIdx.x * blockDim.x + threadIdx.x;
    int stride = gridDim.x * blockDim.x;
    float4 z = make_float4(0.f, 0.f, 0.f, 0.f);
    for (; i < n4; i += stride) p[i] = z;
}

__global__ void zero_flags_kernel(unsigned int* f) { f[0] = 0; f[1] = 0; }

// -------- edge dtype detect (see R13: confirmed working) --------
__global__ void detect_kernel(const unsigned int* __restrict__ buf, int nvals,
                              unsigned int* flag) {
    unsigned int acc = 0;
    int i = blockIdx.x * blockDim.x + threadIdx.x;
    int stride = gridDim.x * blockDim.x;
    for (; i < nvals; i += stride) acc |= buf[2 * i + 1];
#pragma unroll
    for (int o = 16; o; o >>= 1) acc |= __shfl_xor_sync(0xffffffffu, acc, o);
    if ((threadIdx.x & 31) == 0 && acc) atomicOr(flag, acc);
}

__global__ void convert_idx_kernel(const void* __restrict__ buf, int nvals,
                                   const unsigned int* __restrict__ flag,
                                   int* __restrict__ out) {
    bool is32 = (*flag != 0u);
    int i = blockIdx.x * blockDim.x + threadIdx.x;
    int stride = gridDim.x * blockDim.x;
    if (is32) {
        const int* b = (const int*)buf;
        for (; i < nvals; i += stride) out[i] = b[i];
    } else {
        const long long* b = (const long long*)buf;
        for (; i < nvals; i += stride) out[i] = (int)b[i];
    }
}

// -------- 128-dim scatter-add (layer 1): warp per edge, v4 RED --------
__global__ void agg_kernel(const float* __restrict__ x,
                           const int* __restrict__ src,
                           const int* __restrict__ dst,
                           int E, int Nmax, float* __restrict__ agg) {
    int gw = (blockIdx.x * blockDim.x + threadIdx.x) >> 5;
    int lane = threadIdx.x & 31;
    int nw = (gridDim.x * blockDim.x) >> 5;
    for (int e = gw; e < E; e += nw) {
        int s = __ldg(src + e);
        int d = __ldg(dst + e);
        if ((unsigned)s >= (unsigned)Nmax || (unsigned)d >= (unsigned)Nmax) continue;
        float4 v = __ldg((const float4*)(x + (size_t)s * 128) + lane);
        float* p = agg + (size_t)d * 128 + lane * 4;
        asm volatile("red.global.add.v4.f32 [%0], {%1,%2,%3,%4};"
                     :: "l"(p), "f"(v.x), "f"(v.y), "f"(v.z), "f"(v.w)
                     : "memory");
    }
}

// -------- 64-dim scatter-add (layer 2, post-transform): 2 edges/warp ----
// lanes 0-15 -> edge 2p, lanes 16-31 -> edge 2p+1; float4 per lane
__global__ void agg64_kernel(const float* __restrict__ y,
                             const int* __restrict__ src,
                             const int* __restrict__ dst,
                             int E, int Nmax, float* __restrict__ agg) {
    int gw = (blockIdx.x * blockDim.x + threadIdx.x) >> 5;
    int lane = threadIdx.x & 31;
    int nw = (gridDim.x * blockDim.x) >> 5;
    int half = lane >> 4, l16 = lane & 15;
    int npair = (E + 1) >> 1;
    for (int p = gw; p < npair; p += nw) {
        int e = 2 * p + half;
        if (e >= E) continue;
        int s = __ldg(src + e);
        int d = __ldg(dst + e);
        if ((unsigned)s >= (unsigned)Nmax || (unsigned)d >= (unsigned)Nmax) continue;
        float4 v = __ldg((const float4*)(y + (size_t)s * 64) + l16);
        float* ptr = agg + (size_t)d * 64 + l16 * 4;
        asm volatile("red.global.add.v4.f32 [%0], {%1,%2,%3,%4};"
                     :: "l"(ptr), "f"(v.x), "f"(v.y), "f"(v.z), "f"(v.w)
                     : "memory");
    }
}

// -------- fused GIN MLP (layer 1): relu(W2^T relu(W1^T(x+agg)+b1)+b2) ----
template <int C1, int C2>
__global__ void __launch_bounds__(256)
gin_mlp_kernel(const float* __restrict__ x, const float* __restrict__ agg, int M,
               const float* __restrict__ W1, const float* __restrict__ b1,
               const float* __restrict__ W2, const float* __restrict__ b2,
               float* __restrict__ out) {
    const int TM = 64;
    extern __shared__ float sm[];
    float* sW1 = sm;
    float* sW2 = sW1 + 128 * C1;
    float* sb1 = sW2 + C1 * C2;
    float* sb2 = sb1 + C1;
    float* sIn = sb2 + C2;
    float* sT  = sIn + TM * 132;
    int tid = threadIdx.x;

    for (int i = tid; i < 128 * C1 / 4; i += 256)
        ((float4*)sW1)[i] = __ldg((const float4*)W1 + i);
    for (int i = tid; i < C1 * C2 / 4; i += 256)
        ((float4*)sW2)[i] = __ldg((const float4*)W2 + i);
    if (tid < C1) sb1[tid] = b1[tid];
    if (tid < C2) sb2[tid] = b2[tid];

    int numTiles = (M + TM - 1) / TM;
    for (int tile = blockIdx.x; tile < numTiles; tile += gridDim.x) {
        int row0 = tile * TM;
        __syncthreads();
        for (int i = tid; i < TM * 32; i += 256) {
            int r = i >> 5, c = i & 31;
            int row = row0 + r;
            float4 v = make_float4(0.f, 0.f, 0.f, 0.f);
            if (row < M) {
                float4 a = __ldg((const float4*)(x + (size_t)row * 128) + c);
                float4 b = __ldg((const float4*)(agg + (size_t)row * 128) + c);
                v.x = a.x + b.x; v.y = a.y + b.y; v.z = a.z + b.z; v.w = a.w + b.w;
            }
            *((float4*)(sIn + r * 132) + c) = v;
        }
        __syncthreads();
        {
            const int CT = C1 / 4, RT = 256 / CT, RPT = TM / RT;
            int tx = tid % CT, ty = tid / CT;
            unsigned long long acc2[RPT][2];
            {
                unsigned long long b01, b23;
                PACK_F32X2(b01, sb1[4 * tx + 0], sb1[4 * tx + 1]);
                PACK_F32X2(b23, sb1[4 * tx + 2], sb1[4 * tx + 3]);
#pragma unroll
                for (int i = 0; i < RPT; i++) { acc2[i][0] = b01; acc2[i][1] = b23; }
            }
#pragma unroll 4
            for (int k = 0; k < 128; k++) {
                float4 w = *((float4*)(sW1 + k * C1) + tx);
                unsigned long long w01, w23;
                PACK_F32X2(w01, w.x, w.y);
                PACK_F32X2(w23, w.z, w.w);
#pragma unroll
                for (int i = 0; i < RPT; i++) {
                    float a = sIn[(ty * RPT + i) * 132 + k];
                    unsigned long long aa;
                    PACK_F32X2(aa, a, a);
                    FMA_F32X2(acc2[i][0], aa, w01, acc2[i][0]);
                    FMA_F32X2(acc2[i][1], aa, w23, acc2[i][1]);
                }
            }
#pragma unroll
            for (int i = 0; i < RPT; i++) {
                float4 v;
                UNPACK_F32X2(v.x, v.y, acc2[i][0]);
                UNPACK_F32X2(v.z, v.w, acc2[i][1]);
                v.x = fmaxf(v.x, 0.f); v.y = fmaxf(v.y, 0.f);
                v.z = fmaxf(v.z, 0.f); v.w = fmaxf(v.w, 0.f);
                *((float4*)(sT + (ty * RPT + i) * (C1 + 4)) + tx) = v;
            }
        }
        __syncthreads();
        {
            const int CT = C2 / 4, RT = 256 / CT, RPT = TM / RT;
            int tx = tid % CT, ty = tid / CT;
            unsigned long long acc2[RPT][2];
            {
                unsigned long long b01, b23;
                PACK_F32X2(b01, sb2[4 * tx + 0], sb2[4 * tx + 1]);
                PACK_F32X2(b23, sb2[4 * tx + 2], sb2[4 * tx + 3]);
#pragma unroll
                for (int i = 0; i < RPT; i++) { acc2[i][0] = b01; acc2[i][1] = b23; }
            }
#pragma unroll 4
            for (int k = 0; k < C1; k++) {
                float4 w = *((float4*)(sW2 + k * C2) + tx);
                unsigned long long w01, w23;
                PACK_F32X2(w01, w.x, w.y);
                PACK_F32X2(w23, w.z, w.w);
#pragma unroll
                for (int i = 0; i < RPT; i++) {
                    float a = sT[(ty * RPT + i) * (C1 + 4) + k];
                    unsigned long long aa;
                    PACK_F32X2(aa, a, a);
                    FMA_F32X2(acc2[i][0], aa, w01, acc2[i][0]);
                    FMA_F32X2(acc2[i][1], aa, w23, acc2[i][1]);
                }
            }
#pragma unroll
            for (int i = 0; i < RPT; i++) {
                int row = row0 + ty * RPT + i;
                if (row < M) {
                    float4 v;
                    UNPACK_F32X2(v.x, v.y, acc2[i][0]);
                    UNPACK_F32X2(v.z, v.w, acc2[i][1]);
                    v.x = fmaxf(v.x, 0.f); v.y = fmaxf(v.y, 0.f);
                    v.z = fmaxf(v.z, 0.f); v.w = fmaxf(v.w, 0.f);
                    *((float4*)(out + (size_t)row * C2) + tx) = v;
                }
            }
        }
    }
}

// -------- y = x @ W (128 -> 64), no bias/relu (layer-2 pre-transform) ----
__global__ void __launch_bounds__(256)
lin_kernel(const float* __restrict__ x, int M, const float* __restrict__ W,
           float* __restrict__ y) {
    extern __shared__ float sm[];
    float* sW = sm;              // 128*64
    float* sIn = sW + 128 * 64;  // 64*132
    int tid = threadIdx.x;
    for (int i = tid; i < 128 * 64 / 4; i += 256)
        ((float4*)sW)[i] = __ldg((const float4*)W + i);
    int numTiles = (M + 63) / 64;
    for (int tile = blockIdx.x; tile < numTiles; tile += gridDim.x) {
        int row0 = tile * 64;
        __syncthreads();
        for (int i = tid; i < 64 * 32; i += 256) {
            int r = i >> 5, c = i & 31;
            int row = row0 + r;
            float4 v = make_float4(0.f, 0.f, 0.f, 0.f);
            if (row < M) v = __ldg((const float4*)(x + (size_t)row * 128) + c);
            *((float4*)(sIn + r * 132) + c) = v;
        }
        __syncthreads();
        int tx = tid % 16, ty = tid / 16;   // 16 col-groups x 16 row-groups, RPT=4
        unsigned long long acc2[4][2];
#pragma unroll
        for (int i = 0; i < 4; i++) { acc2[i][0] = 0ull; acc2[i][1] = 0ull; }
#pragma unroll 4
        for (int k = 0; k < 128; k++) {
            float4 w = *((float4*)(sW + k * 64) + tx);
            unsigned long long w01, w23;
            PACK_F32X2(w01, w.x, w.y);
            PACK_F32X2(w23, w.z, w.w);
#pragma unroll
            for (int i = 0; i < 4; i++) {
                float a = sIn[(ty * 4 + i) * 132 + k];
                unsigned long long aa;
                PACK_F32X2(aa, a, a);
                FMA_F32X2(acc2[i][0], aa, w01, acc2[i][0]);
                FMA_F32X2(acc2[i][1], aa, w23, acc2[i][1]);
            }
        }
#pragma unroll
        for (int i = 0; i < 4; i++) {
            int row = row0 + ty * 4 + i;
            if (row < M) {
                float4 v;
                UNPACK_F32X2(v.x, v.y, acc2[i][0]);
                UNPACK_F32X2(v.z, v.w, acc2[i][1]);
                *((float4*)(y + (size_t)row * 64) + tx) = v;
            }
        }
    }
}

// -------- out = relu( relu(y + aggy + b1) @ W2 + b2 )  (layer-2 tail) ----
__global__ void __launch_bounds__(256)
mlp2b_kernel(const float* __restrict__ y, const float* __restrict__ aggy, int M,
             const float* __restrict__ b1, const float* __restrict__ W2,
             const float* __restrict__ b2, float* __restrict__ out) {
    __shared__ float sW2[64 * 64];
    __shared__ float sT[64 * 68];
    __shared__ float sb1[64], sb2[64];
    int tid = threadIdx.x;
    for (int i = tid; i < 64 * 64 / 4; i += 256)
        ((float4*)sW2)[i] = __ldg((const float4*)W2 + i);
    if (tid < 64) { sb1[tid] = b1[tid]; sb2[tid] = b2[tid]; }
    int numTiles = (M + 63) / 64;
    for (int tile = blockIdx.x; tile < numTiles; tile += gridDim.x) {
        int row0 = tile * 64;
        __syncthreads();
        for (int i = tid; i < 64 * 16; i += 256) {
            int r = i >> 4, c = i & 15;
            int row = row0 + r;
            float4 v = make_float4(0.f, 0.f, 0.f, 0.f);
            if (row < M) {
                float4 a = __ldg((const float4*)(y + (size_t)row * 64) + c);
                float4 b = __ldg((const float4*)(aggy + (size_t)row * 64) + c);
                v.x = fmaxf(a.x + b.x + sb1[4 * c + 0], 0.f);
                v.y = fmaxf(a.y + b.y + sb1[4 * c + 1], 0.f);
                v.z = fmaxf(a.z + b.z + sb1[4 * c + 2], 0.f);
                v.w = fmaxf(a.w + b.w + sb1[4 * c + 3], 0.f);
            }
            *((float4*)(sT + r * 68) + c) = v;
        }
        __syncthreads();
        int tx = tid % 16, ty = tid / 16;
        unsigned long long acc2[4][2];
        {
            unsigned long long b01, b23;
            PACK_F32X2(b01, sb2[4 * tx + 0], sb2[4 * tx + 1]);
            PACK_F32X2(b23, sb2[4 * tx + 2], sb2[4 * tx + 3]);
#pragma unroll
            for (int i = 0; i < 4; i++) { acc2[i][0] = b01; acc2[i][1] = b23; }
        }
#pragma unroll 4
        for (int k = 0; k < 64; k++) {
            float4 w = *((float4*)(sW2 + k * 64) + tx);
            unsigned long long w01, w23;
            PACK_F32X2(w01, w.x, w.y);
            PACK_F32X2(w23, w.z, w.w);
#pragma unroll
            for (int i = 0; i < 4; i++) {
                float a = sT[(ty * 4 + i) * 68 + k];
                unsigned long long aa;
                PACK_F32X2(aa, a, a);
                FMA_F32X2(acc2[i][0], aa, w01, acc2[i][0]);
                FMA_F32X2(acc2[i][1], aa, w23, acc2[i][1]);
            }
        }
#pragma unroll
        for (int i = 0; i < 4; i++) {
            int row = row0 + ty * 4 + i;
            if (row < M) {
                float4 v;
                UNPACK_F32X2(v.x, v.y, acc2[i][0]);
                UNPACK_F32X2(v.z, v.w, acc2[i][1]);
                v.x = fmaxf(v.x, 0.f); v.y = fmaxf(v.y, 0.f);
                v.z = fmaxf(v.z, 0.f); v.w = fmaxf(v.w, 0.f);
                *((float4*)(out + (size_t)row * 64) + tx) = v;
            }
        }
    }
}

// -------- key[i] = dist(out1[i], out2[198]) --------
__global__ void key_kernel(const float* __restrict__ out1,
                           const float* __restrict__ out2last,
                           float* __restrict__ key, int M) {
    int gw = (blockIdx.x * blockDim.x + threadIdx.x) >> 5;
    int lane = threadIdx.x & 31;
    int nw = (gridDim.x * blockDim.x) >> 5;
    float2 b = ((const float2*)out2last)[lane];
    float n2 = b.x * b.x + b.y * b.y;
#pragma unroll
    for (int o = 16; o; o >>= 1) n2 += __shfl_xor_sync(0xffffffffu, n2, o);
    for (int i = gw; i < M; i += nw) {
        float2 a = __ldg((const float2*)(out1 + (size_t)i * 64) + lane);
        float dot = a.x * b.x + a.y * b.y;
        float n1 = a.x * a.x + a.y * a.y;
#pragma unroll
        for (int o = 16; o; o >>= 1) {
            dot += __shfl_xor_sync(0xffffffffu, dot, o);
            n1 += __shfl_xor_sync(0xffffffffu, n1, o);
        }
        if (lane == 0) key[i] = sqrtf(fmaxf(n1 + n2 - 2.f * dot, 0.f));
    }
}

// -------- exact top-50 per graph --------
__global__ void topk_kernel(const float* __restrict__ key, int* __restrict__ top) {
    extern __shared__ float sk[];
    __shared__ float sval[32];
    __shared__ int sidx[32];
    int g = blockIdx.x, tid = threadIdx.x;
    const float* kg = key + g * NPG;
    for (int i = tid; i < NPG; i += blockDim.x) sk[i] = kg[i];
    __syncthreads();
    for (int r = 0; r < KSEL; r++) {
        float bv = -3.0e38f; int bi = 0x7fffffff;
        for (int i = tid; i < NPG; i += blockDim.x) {
            float v = sk[i];
            if (v > bv || (v == bv && i < bi)) { bv = v; bi = i; }
        }
#pragma unroll
        for (int o = 16; o; o >>= 1) {
            float ov = __shfl_xor_sync(0xffffffffu, bv, o);
            int oi = __shfl_xor_sync(0xffffffffu, bi, o);
            if (ov > bv || (ov == bv && oi < bi)) { bv = ov; bi = oi; }
        }
        int w = tid >> 5;
        if ((tid & 31) == 0) { sval[w] = bv; sidx[w] = bi; }
        __syncthreads();
        if (w == 0) {
            int nwarp = blockDim.x >> 5;
            bv = (tid < nwarp) ? sval[tid] : -3.0e38f;
            bi = (tid < nwarp) ? sidx[tid] : 0x7fffffff;
#pragma unroll
            for (int o = 16; o; o >>= 1) {
                float ov = __shfl_xor_sync(0xffffffffu, bv, o);
                int oi = __shfl_xor_sync(0xffffffffu, bi, o);
                if (ov > bv || (ov == bv && oi < bi)) { bv = ov; bi = oi; }
            }
            if (tid == 0) {
                top[g * KSEL + r] = g * NPG + bi;
                sk[bi] = -3.0e38f;
            }
        }
        __syncthreads();
    }
}

// -------- full distance rows for the 400 selected nodes --------
__global__ void pooled_kernel(const float* __restrict__ out1,
                              const float* __restrict__ out2,
                              const int* __restrict__ top,
                              float* __restrict__ pooled) {
    __shared__ float a[64];
    __shared__ float n1s;
    int slot = blockIdx.x;
    int node = top[slot];
    int tid = threadIdx.x;
    if (tid < 64) a[tid] = out1[(size_t)node * 64 + tid];
    __syncthreads();
    if (tid == 0) {
        float s = 0.f;
        for (int d = 0; d < 64; d++) s += a[d] * a[d];
        n1s = s;
    }
    __syncthreads();
    for (int j = tid; j < NN2; j += blockDim.x) {
        const float* b = out2 + j * 64;
        float dot = 0.f, n2 = 0.f;
#pragma unroll 8
        for (int d = 0; d < 64; d++) {
            float bv = __ldg(b + d);
            dot += a[d] * bv;
            n2 += bv * bv;
        }
        pooled[slot * NN2 + j] = sqrtf(fmaxf(n1s + n2 - 2.f * dot, 0.f));
    }
}

// -------- fc1 partial sums --------
__global__ void fc1_kernel(const float* __restrict__ pooled,
                           const float* __restrict__ W,
                           float* __restrict__ out) {
    int g = blockIdx.x, kc = blockIdx.y, c = threadIdx.x;
    int k0 = kc * 1244;
    int k1 = k0 + 1244; if (k1 > 9950) k1 = 9950;
    const float* p = pooled + g * 9950;
    float acc = 0.f;
    for (int k = k0; k < k1; k++) acc += __ldg(p + k) * __ldg(W + (size_t)k * 128 + c);
    atomicAdd(&out[g * 128 + c], acc);
}

// -------- head --------
__device__ __forceinline__ float block_sum(float v, volatile float* red) {
#pragma unroll
    for (int o = 16; o; o >>= 1) v += __shfl_xor_sync(0xffffffffu, v, o);
    int w = threadIdx.x >> 5;
    if ((threadIdx.x & 31) == 0) red[w] = v;
    __syncthreads();
    float s = red[0] + red[1] + red[2] + red[3];
    __syncthreads();
    return s;
}

__global__ void head_kernel(const float* __restrict__ fc1acc, const float* __restrict__ fc1b,
                            const float* __restrict__ g1, const float* __restrict__ be1,
                            const float* __restrict__ fc2W, const float* __restrict__ fc2b,
                            const float* __restrict__ g2, const float* __restrict__ be2,
                            const float* __restrict__ fc3W, const float* __restrict__ fc3b,
                            float* __restrict__ outp) {
    __shared__ float sh[128];
    __shared__ float red[4];
    int g = blockIdx.x, tid = threadIdx.x;
    float v = fc1acc[g * 128 + tid] + fc1b[tid];
    float mean = block_sum(v, red) * (1.f / 128.f);
    float d = v - mean;
    float var = block_sum(d * d, red) * (1.f / 128.f);
    float h = fmaxf(d * rsqrtf(var + 1e-5f) * g1[tid] + be1[tid], 0.f);
    sh[tid] = h;
    __syncthreads();
    float v2 = 0.f;
    if (tid < 64) {
        v2 = fc2b[tid];
        for (int k = 0; k < 128; k++) v2 += sh[k] * fc2W[k * 64 + tid];
    }
    float s2 = block_sum(tid < 64 ? v2 : 0.f, red);
    float mean2 = s2 * (1.f / 64.f);
    float d2 = v2 - mean2;
    float var2 = block_sum(tid < 64 ? d2 * d2 : 0.f, red) * (1.f / 64.f);
    float t = 0.f;
    if (tid < 64) {
        float h2 = fmaxf(d2 * rsqrtf(var2 + 1e-5f) * g2[tid] + be2[tid], 0.f);
        t = h2 * fc3W[tid];
    }
    float z = block_sum(t, red);
    if (tid == 0) outp[g] = 1.f / (1.f + expf(-(z + fc3b[0])));
}

// ========================= launch ========================================
extern "C" void kernel_launch(void* const* d_in, const int* in_sizes, int n_in,
                              void* d_out, int out_size) {
    const float* x1 = (const float*)d_in[0];
    const void* ei1raw = d_in[1];
    const float* x2 = (const float*)d_in[3];
    const void* ei2raw = d_in[4];
    const float* W1a = (const float*)d_in[5];
    const float* b1a = (const float*)d_in[6];
    const float* W1b = (const float*)d_in[7];
    const float* b1b = (const float*)d_in[8];
    const float* W2a = (const float*)d_in[9];
    const float* b2a = (const float*)d_in[10];
    const float* W2b = (const float*)d_in[11];
    const float* b2b = (const float*)d_in[12];
    const float* fc1W = (const float*)d_in[13];
    const float* fc1b = (const float*)d_in[14];
    const float* g1v = (const float*)d_in[15];
    const float* be1 = (const float*)d_in[16];
    const float* fc2W = (const float*)d_in[17];
    const float* fc2b = (const float*)d_in[18];
    const float* g2v = (const float*)d_in[19];
    const float* be2 = (const float*)d_in[20];
    const float* fc3W = (const float*)d_in[21];
    const float* fc3b = (const float*)d_in[22];
    float* outp = (float*)d_out;

    int n1v = in_sizes[1];
    int n2v = in_sizes[4];
    int E1v = n1v / 2;
    int E2v = n2v / 2;

    float *agg, *h, *out1, *agg2, *h2, *out2, *keyp, *pooled, *fc1acc;
    int *top, *ei1c, *ei2c;
    unsigned int* flags;
    cudaGetSymbolAddress((void**)&agg, g_agg);
    cudaGetSymbolAddress((void**)&h, g_h);
    cudaGetSymbolAddress((void**)&out1, g_out1);
    cudaGetSymbolAddress((void**)&agg2, g_agg2);
    cudaGetSymbolAddress((void**)&h2, g_h2);
    cudaGetSymbolAddress((void**)&out2, g_out2);
    cudaGetSymbolAddress((void**)&keyp, g_key);
    cudaGetSymbolAddress((void**)&top, g_top);
    cudaGetSymbolAddress((void**)&pooled, g_pooled);
    cudaGetSymbolAddress((void**)&fc1acc, g_fc1);
    cudaGetSymbolAddress((void**)&ei1c, g_ei1);
    cudaGetSymbolAddress((void**)&ei2c, g_ei2);
    cudaGetSymbolAddress((void**)&flags, g_flag);

    // layer-2 scratch carved from g_agg / g_agg2 (after layer 1 is done)
    float* y1    = agg;
    float* aggy1 = agg + (size_t)N1 * 64;
    float* y2    = agg2;
    float* aggy2 = agg2 + (size_t)NN2 * 64;

    const int nsm = 152;  // GB300 sm_103a

    size_t smem1 = (size_t)(128 * 128 + 128 * 128 + 128 + 128 + 64 * 132 + 64 * 132) * sizeof(float);
    size_t smemL = (size_t)(128 * 64 + 64 * 132) * sizeof(float);
    cudaFuncSetAttribute(gin_mlp_kernel<128, 128>,
                         cudaFuncAttributeMaxDynamicSharedMemorySize, (int)smem1);
    cudaFuncSetAttribute(lin_kernel,
                         cudaFuncAttributeMaxDynamicSharedMemorySize, (int)smemL);
    cudaFuncSetAttribute(topk_kernel,
                         cudaFuncAttributeMaxDynamicSharedMemorySize, NPG * 4);

    // ---- edge-index dtype detection + canonicalization to int32 ----
    zero_flags_kernel<<<1, 1>>>(flags);
    detect_kernel<<<256, 256>>>((const unsigned int*)ei1raw, n1v / 2, flags + 0);
    detect_kernel<<<16, 256>>>((const unsigned int*)ei2raw, n2v / 2, flags + 1);
    convert_idx_kernel<<<1024, 256>>>(ei1raw, n1v, flags + 0, ei1c);
    convert_idx_kernel<<<16, 256>>>(ei2raw, n2v, flags + 1, ei2c);

    // ---- graph 1: GIN layer 1 (fused) ----
    zero_kernel<<<2048, 256>>>((float4*)agg, N1 * 32);
    agg_kernel<<<2048, 256>>>(x1, ei1c, ei1c + E1v, E1v, N1, agg);
    gin_mlp_kernel<128, 128><<<imin(3125, nsm), 256, smem1>>>(x1, agg, N1, W1a, b1a, W1b, b1b, h);

    // ---- graph 1: GIN layer 2 via linearity (aggregate in 64-dim) ----
    lin_kernel<<<imin(3125, 3 * nsm), 256, smemL>>>(h, N1, W2a, y1);
    zero_kernel<<<1024, 256>>>((float4*)aggy1, N1 * 16);
    agg64_kernel<<<2048, 256>>>(y1, ei1c, ei1c + E1v, E1v, N1, aggy1);
    mlp2b_kernel<<<imin(3125, 4 * nsm), 256>>>(y1, aggy1, N1, b2a, W2b, b2b, out1);

    // ---- graph 2 (tiny), same structure ----
    zero_kernel<<<32, 256>>>((float4*)agg2, NN2 * 32);
    agg_kernel<<<16, 256>>>(x2, ei2c, ei2c + E2v, E2v, NN2, agg2);
    gin_mlp_kernel<128, 128><<<4, 256, smem1>>>(x2, agg2, NN2, W1a, b1a, W1b, b1b, h2);
    lin_kernel<<<4, 256, smemL>>>(h2, NN2, W2a, y2);
    zero_kernel<<<16, 256>>>((float4*)aggy2, NN2 * 16);
    agg64_kernel<<<16, 256>>>(y2, ei2c, ei2c + E2v, E2v, NN2, aggy2);
    mlp2b_kernel<<<4, 256>>>(y2, aggy2, NN2, b2a, W2b, b2b, out2);

    // ---- sort-pool shortcut ----
    key_kernel<<<1024, 256>>>(out1, out2 + 198 * 64, keyp, N1);
    topk_kernel<<<8, 1024, NPG * 4>>>(keyp, top);
    pooled_kernel<<<400, 256>>>(out1, out2, top, pooled);

    // ---- head ----
    zero_kernel<<<1, 256>>>((float4*)fc1acc, 8 * 32);
    fc1_kernel<<<dim3(8, 8), 128>>>(pooled, fc1W, fc1acc);
    head_kernel<<<8, 128>>>(fc1acc, fc1b, g1v, be1, fc2W, fc2b, g2v, be2, fc3W, fc3b, outp);
}